// round 4
// baseline (speedup 1.0000x reference)
#include <cuda_runtime.h>
#include <cuda_bf16.h>
#include <math.h>

#define BATCH   16384
#define HID     256
#define LAT     64
#define NBLOCKS 3
#define NSTEPS  63   // T-1

typedef unsigned long long ull;

// ---------------- scratch (static device globals; no runtime allocation) ----
__device__ float g_bufA[BATCH * HID];    // 16 MB
__device__ float g_bufB[BATCH * HID];    // 16 MB
__device__ float g_z[BATCH * LAT];       // 4 MB
__device__ float g_drift[BATCH * LAT];   // 4 MB

// ---------------- packed f32x2 helpers (Blackwell FFMA2 path) --------------
__device__ __forceinline__ ull pack2(float x, float y) {
    ull r;
    asm("mov.b64 %0, {%1, %2};" : "=l"(r) : "f"(x), "f"(y));
    return r;
}
__device__ __forceinline__ void unpack2(ull v, float& x, float& y) {
    asm("mov.b64 {%0, %1}, %2;" : "=f"(x), "=f"(y) : "l"(v));
}
__device__ __forceinline__ void ffma2(ull& d, ull a, ull b) {
    // d = a * b + d, elementwise on packed {lo,hi} f32 pairs (SASS FFMA2)
    asm("fma.rn.f32x2 %0, %1, %2, %0;" : "+l"(d) : "l"(a), "l"(b));
}

__device__ __forceinline__ float swish_f(float x) {
    return x / (1.0f + expf(-x));
}
__device__ __forceinline__ float softplus_f(float x) {
    // numerically stable, matches jax.nn.softplus
    return fmaxf(x, 0.0f) + log1pf(expf(-fabsf(x)));
}

// ---------------- epilogue codes -------------------------------------------
constexpr int EPI_NONE   = 0;  // C = acc + b
constexpr int EPI_SWISH  = 1;  // C = swish(acc + b)
constexpr int EPI_RES    = 2;  // C = res + acc + b
constexpr int EPI_TSWISH = 3;  // C = swish(acc + b + t*w0[c])   (t-column folded)
constexpr int EPI_LATENT = 4;  // c<64 -> mu ; c>=64 -> s = exp(0.5*(acc+b))
constexpr int EPI_Z0     = 5;  // write z scratch AND z_path[0]
constexpr int EPI_UPDATE = 6;  // z_new = z + drift*dt + softplus(acc+b)*sqrt(dt)*noise

template <int EPI>
__device__ __forceinline__ void epi_elem(
    float v, int r, int c,
    const float* __restrict__ bias,
    const float* __restrict__ res,
    const float* __restrict__ w0,
    float t, float dt, float sd,
    const float* __restrict__ noise,
    const float* __restrict__ zin,
    const float* __restrict__ dr,
    float* __restrict__ C, int ldc,
    float* __restrict__ out2)
{
    float xv = v + bias[c];
    if constexpr (EPI == EPI_NONE) {
        C[(size_t)r * ldc + c] = xv;
    } else if constexpr (EPI == EPI_SWISH) {
        C[(size_t)r * ldc + c] = swish_f(xv);
    } else if constexpr (EPI == EPI_RES) {
        C[(size_t)r * ldc + c] = xv + res[(size_t)r * ldc + c];
    } else if constexpr (EPI == EPI_TSWISH) {
        C[(size_t)r * ldc + c] = swish_f(xv + t * w0[c]);
    } else if constexpr (EPI == EPI_LATENT) {
        if (c < LAT) C[(size_t)r * LAT + c] = xv;
        else         out2[(size_t)r * LAT + (c - LAT)] = expf(0.5f * xv);
    } else if constexpr (EPI == EPI_Z0) {
        size_t idx = (size_t)r * LAT + c;
        C[idx] = xv;
        out2[idx] = xv;
    } else if constexpr (EPI == EPI_UPDATE) {
        size_t idx = (size_t)r * LAT + c;
        float g  = softplus_f(xv);
        float zn = zin[idx] + dr[idx] * dt + g * sd * noise[idx];
        C[idx]   = zn;   // z scratch
        out2[idx] = zn;  // z_path[step+1]
    }
}

// ---------------- tiled fp32 GEMM using packed FFMA2 -----------------------
// C[M,N] = epi( A[M,K] @ W[K,N] + bias )
// A row-major (lda), W row-major (ldw = global N of the weight).
// BM=128, BK=8, 256 threads. TNP = packed col-pairs per thread:
//   TNP=4 -> BN=128, 8x8 microtile;  TNP=2 -> BN=64, 8x4 microtile.
template <int TNP, int EPI>
__global__ __launch_bounds__(256, 2)
void gemm_k(const float* __restrict__ A, int lda, int K,
            const float* __restrict__ W, int ldw,
            const float* __restrict__ bias,
            float* __restrict__ C, int ldc,
            const float* __restrict__ res,
            const float* __restrict__ w0,
            const float* __restrict__ ts, int step,
            const float* __restrict__ noise,
            const float* __restrict__ zin,
            const float* __restrict__ dr,
            float* __restrict__ out2)
{
    constexpr int BM = 128;
    constexpr int BK = 8;
    constexpr int TM = 8;
    constexpr int TN = 2 * TNP;
    constexpr int BN = 16 * TN;

    __shared__ __align__(16) ull   As2[BK][BM];  // A duplicated as {a,a} pairs
    __shared__ __align__(16) float Ws[BK][BN];

    const int tid = threadIdx.x;
    const int tx  = tid & 15;
    const int ty  = tid >> 4;
    const int row0 = blockIdx.y * BM;
    const int col0 = blockIdx.x * BN;

    // A tile load mapping: thread -> (row, 4-col chunk)
    const int a_row = tid >> 1;
    const int a_col = (tid & 1) * 4;
    const float* Aptr = A + (size_t)(row0 + a_row) * lda + a_col;

    ull acc[TM][TNP];
#pragma unroll
    for (int i = 0; i < TM; ++i)
#pragma unroll
        for (int j = 0; j < TNP; ++j) acc[i][j] = 0ull;

    for (int k0 = 0; k0 < K; k0 += BK) {
        // --- stage A tile (transposed, duplicated into f32x2 pairs) ---
        float4 av = *reinterpret_cast<const float4*>(Aptr + k0);
        As2[a_col + 0][a_row] = pack2(av.x, av.x);
        As2[a_col + 1][a_row] = pack2(av.y, av.y);
        As2[a_col + 2][a_row] = pack2(av.z, av.z);
        As2[a_col + 3][a_row] = pack2(av.w, av.w);

        // --- stage W tile (coalesced, n-contiguous) ---
        if (TNP == 4) {
            int wr = tid >> 5, wc = (tid & 31) * 4;
            *reinterpret_cast<float4*>(&Ws[wr][wc]) =
                *reinterpret_cast<const float4*>(W + (size_t)(k0 + wr) * ldw + col0 + wc);
        } else {
            if (tid < 128) {
                int wr = tid >> 4, wc = (tid & 15) * 4;
                *reinterpret_cast<float4*>(&Ws[wr][wc]) =
                    *reinterpret_cast<const float4*>(W + (size_t)(k0 + wr) * ldw + col0 + wc);
            }
        }
        __syncthreads();

#pragma unroll
        for (int kk = 0; kk < BK; ++kk) {
            ull areg[TM];
#pragma unroll
            for (int i = 0; i < TM; i += 2) {
                ulonglong2 t2 = *reinterpret_cast<const ulonglong2*>(&As2[kk][ty * TM + i]);
                areg[i] = t2.x;
                areg[i + 1] = t2.y;
            }
            ull breg[TNP];
#pragma unroll
            for (int j = 0; j < TNP; j += 2) {
                ulonglong2 t2 = *reinterpret_cast<const ulonglong2*>(&Ws[kk][tx * TN + 2 * j]);
                breg[j] = t2.x;
                breg[j + 1] = t2.y;
            }
#pragma unroll
            for (int i = 0; i < TM; ++i)
#pragma unroll
                for (int j = 0; j < TNP; ++j)
                    ffma2(acc[i][j], areg[i], breg[j]);
        }
        __syncthreads();
    }

    // --- epilogue ---
    float t = 0.f, dt = 0.f, sd = 0.f;
    if constexpr (EPI == EPI_TSWISH) {
        t = ts[step];
    }
    if constexpr (EPI == EPI_UPDATE) {
        float t0 = ts[step];
        dt = ts[step + 1] - t0;
        sd = sqrtf(dt);
    }

    const int rbase = row0 + ty * TM;
    const int cbase = col0 + tx * TN;
#pragma unroll
    for (int i = 0; i < TM; ++i) {
        int r = rbase + i;
#pragma unroll
        for (int j = 0; j < TNP; ++j) {
            float vx, vy;
            unpack2(acc[i][j], vx, vy);
            int c = cbase + 2 * j;
            epi_elem<EPI>(vx, r, c,     bias, res, w0, t, dt, sd, noise, zin, dr, C, ldc, out2);
            epi_elem<EPI>(vy, r, c + 1, bias, res, w0, t, dt, sd, noise, zin, dr, C, ldc, out2);
        }
    }
}

// ---------------- host driver ----------------------------------------------
extern "C" void kernel_launch(void* const* d_in, const int* in_sizes, int n_in,
                              void* d_out, int out_size)
{
    (void)in_sizes; (void)n_in; (void)out_size;

    const float* x      = (const float*)d_in[0];
    const float* ts     = (const float*)d_in[1];
    const float* noise  = (const float*)d_in[2];
    const float* W_in   = (const float*)d_in[3];
    const float* b_in   = (const float*)d_in[4];
    const float* Wb1    = (const float*)d_in[5];
    const float* bb1    = (const float*)d_in[6];
    const float* Wb2    = (const float*)d_in[7];
    const float* bb2    = (const float*)d_in[8];
    const float* W_fo   = (const float*)d_in[9];
    const float* b_fo   = (const float*)d_in[10];
    const float* W_lat  = (const float*)d_in[11];
    const float* b_lat  = (const float*)d_in[12];
    const float* W_init = (const float*)d_in[13];
    const float* b_init = (const float*)d_in[14];
    const float* Wd1    = (const float*)d_in[15];
    const float* bd1    = (const float*)d_in[16];
    const float* Wd2    = (const float*)d_in[17];
    const float* bd2    = (const float*)d_in[18];
    const float* Wd3    = (const float*)d_in[19];
    const float* bd3    = (const float*)d_in[20];
    const float* Wg1    = (const float*)d_in[21];
    const float* bg1    = (const float*)d_in[22];
    const float* Wg2    = (const float*)d_in[23];
    const float* bg2    = (const float*)d_in[24];

    float* out    = (float*)d_out;
    float* out_mu = out;
    float* out_s  = out + (size_t)BATCH * LAT;
    float* out_zp = out + (size_t)2 * BATCH * LAT;  // z_path[t] = out_zp + t*BATCH*LAT

    float *bufA, *bufB, *z, *drift;
    cudaGetSymbolAddress((void**)&bufA,  g_bufA);
    cudaGetSymbolAddress((void**)&bufB,  g_bufB);
    cudaGetSymbolAddress((void**)&z,     g_z);
    cudaGetSymbolAddress((void**)&drift, g_drift);

    const dim3 blk(256);
    const dim3 g2(2, BATCH / 128);  // BN=128 kernels, N=256 (or N=128 via TNP=2)
    const dim3 g1(1, BATCH / 128);  // BN=64 kernels,  N=64

    const float* NP = nullptr;

    // ---------------- encoder ----------------
    // h = swish(x @ W_in + b_in)
    gemm_k<4, EPI_SWISH><<<g2, blk>>>(x, HID, HID, W_in, HID, b_in, bufA, HID,
                                      NP, NP, NP, 0, NP, NP, NP, nullptr);
    // residual blocks
    for (int i = 0; i < NBLOCKS; ++i) {
        gemm_k<4, EPI_SWISH><<<g2, blk>>>(bufA, HID, HID, Wb1 + (size_t)i * HID * HID, HID,
                                          bb1 + (size_t)i * HID, bufB, HID,
                                          NP, NP, NP, 0, NP, NP, NP, nullptr);
        gemm_k<4, EPI_RES><<<g2, blk>>>(bufB, HID, HID, Wb2 + (size_t)i * HID * HID, HID,
                                        bb2 + (size_t)i * HID, bufA, HID,
                                        bufA, NP, NP, 0, NP, NP, NP, nullptr);
    }
    // features = h @ W_fo + b_fo
    gemm_k<4, EPI_NONE><<<g2, blk>>>(bufA, HID, HID, W_fo, HID, b_fo, bufB, HID,
                                     NP, NP, NP, 0, NP, NP, NP, nullptr);
    // latent_params -> mu, s   (N=128 via two BN=64 blocks)
    gemm_k<2, EPI_LATENT><<<g2, blk>>>(bufB, HID, HID, W_lat, 2 * LAT, b_lat, out_mu, LAT,
                                       NP, NP, NP, 0, NP, NP, NP, out_s);
    // z0 = features @ W_init + b_init  -> z scratch and z_path[0]
    gemm_k<2, EPI_Z0><<<g1, blk>>>(bufB, HID, HID, W_init, LAT, b_init, z, LAT,
                                   NP, NP, NP, 0, NP, NP, NP, out_zp);

    // ---------------- SDE integration ----------------
    // tz @ W1 = z @ W1[1:] + t*W1[0]  -> t-column folded into epilogue bias
    for (int s = 0; s < NSTEPS; ++s) {
        // drift hidden 1: swish(z @ Wd1[1:] + bd1 + t*Wd1[0])
        gemm_k<4, EPI_TSWISH><<<g2, blk>>>(z, LAT, LAT, Wd1 + HID, HID, bd1, bufA, HID,
                                           NP, Wd1, ts, s, NP, NP, NP, nullptr);
        // drift hidden 2: swish(h1 @ Wd2 + bd2)
        gemm_k<4, EPI_SWISH><<<g2, blk>>>(bufA, HID, HID, Wd2, HID, bd2, bufB, HID,
                                          NP, NP, NP, 0, NP, NP, NP, nullptr);
        // drift out: h2 @ Wd3 + bd3
        gemm_k<2, EPI_NONE><<<g1, blk>>>(bufB, HID, HID, Wd3, LAT, bd3, drift, LAT,
                                         NP, NP, NP, 0, NP, NP, NP, nullptr);
        // diffusion hidden: swish(z @ Wg1[1:] + bg1 + t*Wg1[0])
        gemm_k<4, EPI_TSWISH><<<g2, blk>>>(z, LAT, LAT, Wg1 + HID, HID, bg1, bufA, HID,
                                           NP, Wg1, ts, s, NP, NP, NP, nullptr);
        // diffusion out + fused Euler-Maruyama update + z_path write
        gemm_k<2, EPI_UPDATE><<<g1, blk>>>(bufA, HID, HID, Wg2, LAT, bg2, z, LAT,
                                           NP, NP, ts, s,
                                           noise + (size_t)s * BATCH * LAT,
                                           z, drift,
                                           out_zp + (size_t)(s + 1) * BATCH * LAT);
    }
}

// round 8
// speedup vs baseline: 1.2115x; 1.2115x over previous
#include <cuda_runtime.h>
#include <cuda_bf16.h>
#include <math.h>

#define BATCH   16384
#define HID     256
#define LAT     64
#define NBLOCKS 3
#define NSTEPS  63   // T-1

typedef unsigned long long ull;

// ---------------- scratch (static device globals; no runtime allocation) ----
__device__ float g_bufA[BATCH * HID];
__device__ float g_bufB[BATCH * HID];
__device__ float g_bufC[BATCH * HID];
__device__ float g_z[BATCH * LAT];
__device__ float g_drift[BATCH * LAT];

// ---------------- packed f32x2 helpers (Blackwell FFMA2 path) --------------
__device__ __forceinline__ ull pack2(float x, float y) {
    ull r;
    asm("mov.b64 %0, {%1, %2};" : "=l"(r) : "f"(x), "f"(y));
    return r;
}
__device__ __forceinline__ void unpack2(ull v, float& x, float& y) {
    asm("mov.b64 {%0, %1}, %2;" : "=f"(x), "=f"(y) : "l"(v));
}
__device__ __forceinline__ void ffma2(ull& d, ull a, ull b) {
    asm("fma.rn.f32x2 %0, %1, %2, %0;" : "+l"(d) : "l"(a), "l"(b));
}

__device__ __forceinline__ float swish_f(float x) {
    return x / (1.0f + expf(-x));
}
__device__ __forceinline__ float softplus_f(float x) {
    return fmaxf(x, 0.0f) + log1pf(expf(-fabsf(x)));
}

// ---------------- epilogue codes -------------------------------------------
constexpr int EPI_NONE   = 0;
constexpr int EPI_SWISH  = 1;
constexpr int EPI_RES    = 2;
constexpr int EPI_TSWISH = 3;
constexpr int EPI_LATENT = 4;
constexpr int EPI_Z0     = 5;
constexpr int EPI_UPDATE = 6;

template <int EPI>
__device__ __forceinline__ void epi_elem(
    float v, int r, int c,
    const float* __restrict__ bias,
    const float* __restrict__ res,
    const float* __restrict__ w0,
    float t, float dt, float sd,
    const float* __restrict__ noise,
    const float* __restrict__ zin,
    const float* __restrict__ dr,
    float* __restrict__ C, int ldc,
    float* __restrict__ out2)
{
    float xv = v + bias[c];
    if constexpr (EPI == EPI_NONE) {
        C[(size_t)r * ldc + c] = xv;
    } else if constexpr (EPI == EPI_SWISH) {
        C[(size_t)r * ldc + c] = swish_f(xv);
    } else if constexpr (EPI == EPI_RES) {
        C[(size_t)r * ldc + c] = xv + res[(size_t)r * ldc + c];
    } else if constexpr (EPI == EPI_TSWISH) {
        C[(size_t)r * ldc + c] = swish_f(xv + t * w0[c]);
    } else if constexpr (EPI == EPI_LATENT) {
        if (c < LAT) C[(size_t)r * LAT + c] = xv;
        else         out2[(size_t)r * LAT + (c - LAT)] = expf(0.5f * xv);
    } else if constexpr (EPI == EPI_Z0) {
        size_t idx = (size_t)r * LAT + c;
        C[idx] = xv;
        out2[idx] = xv;
    } else if constexpr (EPI == EPI_UPDATE) {
        size_t idx = (size_t)r * LAT + c;
        float g  = softplus_f(xv);
        float zn = zin[idx] + dr[idx] * dt + g * sd * noise[idx];
        C[idx]   = zn;
        out2[idx] = zn;
    }
}

// ---------------- double-buffered conflict-free FFMA2 GEMM -----------------
// C[M,N] = epi( A[M,K] @ W[K,N] + bias )
// 256 threads, 16x16 thread grid. Accumulator packed along M (row pairs).
//   TM  : rows per thread (8 -> BM=128, 4 -> BM=64), must be mult of 4
//   NB  : column-pair groups per thread (4 -> BN=128, 2 -> BN=64)
// A in smem natural floats (row-pairs load as ull broadcasts, no conflicts).
// W in smem pre-duplicated {b,b} ull, interleaved columns (2*tx + 32*g)
// so every load/store hits consecutive lanes -> conflict-free.
template <int TM, int NB, int EPI, bool DUAL>
__global__ __launch_bounds__(256, 2)
void gemm_k(const float* __restrict__ A, int lda, int K,
            const float* __restrict__ W, int ldw,
            const float* __restrict__ bias,
            float* __restrict__ C, int ldc,
            const float* __restrict__ res,
            const float* __restrict__ w0,
            const float* __restrict__ ts, int step,
            const float* __restrict__ noise,
            const float* __restrict__ zin,
            const float* __restrict__ dr,
            float* __restrict__ out2,
            const float* __restrict__ W2,
            const float* __restrict__ bias2,
            const float* __restrict__ w02,
            float* __restrict__ C2)
{
    constexpr int BK = 8;
    constexpr int BM = 16 * TM;
    constexpr int BN = 32 * NB;
    constexpr int TN = 2 * NB;

    __shared__ __align__(16) float As[2][BK][BM + 4];   // +4 pad: conflict-free stores
    __shared__ __align__(16) ull   Ws2[2][BK][BN];      // duplicated pairs

    const int tid = threadIdx.x;
    const int tx  = tid & 15;
    const int ty  = tid >> 4;
    const int row0 = blockIdx.y * BM;
    int col0 = blockIdx.x * BN;

    if constexpr (DUAL) {
        if (blockIdx.x >= 2) { W = W2; bias = bias2; w0 = w02; C = C2; }
        col0 = (blockIdx.x & 1) * BN;
    }

    // --- A stage-load mapping: 2 threads per row, float4 each (BM*8 floats) ---
    const bool a_act = (tid < 2 * BM);
    const int a_row = tid >> 1;
    const int a_kc  = (tid & 1) * 4;
    const float* Ap = A + (size_t)(row0 + a_row) * lda + a_kc;

    // --- W stage-load mapping: row = tid>>5, cols (tid&31) + 32*i ---
    const int w_r  = tid >> 5;
    const int w_c0 = tid & 31;
    const float* Wp = W + (size_t)w_r * ldw + col0 + w_c0;

    float4 ra;
    float  rw[NB];

    // prologue: load + store stage 0
    if (a_act) ra = *reinterpret_cast<const float4*>(Ap);
#pragma unroll
    for (int i = 0; i < NB; ++i) rw[i] = Wp[32 * i];

    if (a_act) {
        As[0][a_kc + 0][a_row] = ra.x;
        As[0][a_kc + 1][a_row] = ra.y;
        As[0][a_kc + 2][a_row] = ra.z;
        As[0][a_kc + 3][a_row] = ra.w;
    }
#pragma unroll
    for (int i = 0; i < NB; ++i) Ws2[0][w_r][w_c0 + 32 * i] = pack2(rw[i], rw[i]);
    __syncthreads();

    ull acc[TM / 2][TN];
#pragma unroll
    for (int i = 0; i < TM / 2; ++i)
#pragma unroll
        for (int j = 0; j < TN; ++j) acc[i][j] = 0ull;

    const int nst = K / BK;
    for (int s = 0; s < nst; ++s) {
        const int buf = s & 1;
        const bool has_next = (s + 1 < nst);

        // prefetch next stage from global while computing this one
        if (has_next) {
            const int k0 = (s + 1) * BK;
            if (a_act) ra = *reinterpret_cast<const float4*>(Ap + k0);
#pragma unroll
            for (int i = 0; i < NB; ++i) rw[i] = Wp[(size_t)k0 * ldw + 32 * i];
        }

#pragma unroll
        for (int kk = 0; kk < BK; ++kk) {
            ull areg[TM / 2];
            ull breg[TN];
#pragma unroll
            for (int p = 0; p < TM / 4; ++p) {
                ulonglong2 t2 = *reinterpret_cast<const ulonglong2*>(
                    &As[buf][kk][ty * TM + 4 * p]);
                areg[2 * p]     = t2.x;   // rows (.., ..+1) pair
                areg[2 * p + 1] = t2.y;   // rows (..+2, ..+3) pair
            }
#pragma unroll
            for (int g = 0; g < NB; ++g) {
                ulonglong2 t2 = *reinterpret_cast<const ulonglong2*>(
                    &Ws2[buf][kk][2 * tx + 32 * g]);
                breg[2 * g]     = t2.x;   // dup of col 2tx+32g
                breg[2 * g + 1] = t2.y;   // dup of col 2tx+32g+1
            }
#pragma unroll
            for (int i = 0; i < TM / 2; ++i)
#pragma unroll
                for (int j = 0; j < TN; ++j)
                    ffma2(acc[i][j], areg[i], breg[j]);
        }

        if (has_next) {
            const int nb = buf ^ 1;
            if (a_act) {
                As[nb][a_kc + 0][a_row] = ra.x;
                As[nb][a_kc + 1][a_row] = ra.y;
                As[nb][a_kc + 2][a_row] = ra.z;
                As[nb][a_kc + 3][a_row] = ra.w;
            }
#pragma unroll
            for (int i = 0; i < NB; ++i) Ws2[nb][w_r][w_c0 + 32 * i] = pack2(rw[i], rw[i]);
            __syncthreads();
        }
    }

    // --- epilogue ---
    float t = 0.f, dt = 0.f, sd = 0.f;
    if constexpr (EPI == EPI_TSWISH || DUAL) {
        t = ts[step];
    }
    if constexpr (EPI == EPI_UPDATE) {
        float t0 = ts[step];
        dt = ts[step + 1] - t0;
        sd = sqrtf(dt);
    }

    const int rb = row0 + ty * TM;
#pragma unroll
    for (int i = 0; i < TM / 2; ++i) {
#pragma unroll
        for (int j = 0; j < TN; ++j) {
            float vx, vy;
            unpack2(acc[i][j], vx, vy);
            const int c = col0 + 2 * tx + 32 * (j >> 1) + (j & 1);
            epi_elem<EPI>(vx, rb + 2 * i,     c, bias, res, w0, t, dt, sd, noise, zin, dr, C, ldc, out2);
            epi_elem<EPI>(vy, rb + 2 * i + 1, c, bias, res, w0, t, dt, sd, noise, zin, dr, C, ldc, out2);
        }
    }
}

// ---------------- host driver ----------------------------------------------
extern "C" void kernel_launch(void* const* d_in, const int* in_sizes, int n_in,
                              void* d_out, int out_size)
{
    (void)in_sizes; (void)n_in; (void)out_size;

    const float* x      = (const float*)d_in[0];
    const float* ts     = (const float*)d_in[1];
    const float* noise  = (const float*)d_in[2];
    const float* W_in   = (const float*)d_in[3];
    const float* b_in   = (const float*)d_in[4];
    const float* Wb1    = (const float*)d_in[5];
    const float* bb1    = (const float*)d_in[6];
    const float* Wb2    = (const float*)d_in[7];
    const float* bb2    = (const float*)d_in[8];
    const float* W_fo   = (const float*)d_in[9];
    const float* b_fo   = (const float*)d_in[10];
    const float* W_lat  = (const float*)d_in[11];
    const float* b_lat  = (const float*)d_in[12];
    const float* W_init = (const float*)d_in[13];
    const float* b_init = (const float*)d_in[14];
    const float* Wd1    = (const float*)d_in[15];
    const float* bd1    = (const float*)d_in[16];
    const float* Wd2    = (const float*)d_in[17];
    const float* bd2    = (const float*)d_in[18];
    const float* Wd3    = (const float*)d_in[19];
    const float* bd3    = (const float*)d_in[20];
    const float* Wg1    = (const float*)d_in[21];
    const float* bg1    = (const float*)d_in[22];
    const float* Wg2    = (const float*)d_in[23];
    const float* bg2    = (const float*)d_in[24];

    float* out    = (float*)d_out;
    float* out_mu = out;
    float* out_s  = out + (size_t)BATCH * LAT;
    float* out_zp = out + (size_t)2 * BATCH * LAT;   // z_path[t] = out_zp + t*BATCH*LAT

    float *bufA, *bufB, *bufC, *z, *drift;
    cudaGetSymbolAddress((void**)&bufA,  g_bufA);
    cudaGetSymbolAddress((void**)&bufB,  g_bufB);
    cudaGetSymbolAddress((void**)&bufC,  g_bufC);
    cudaGetSymbolAddress((void**)&z,     g_z);
    cudaGetSymbolAddress((void**)&drift, g_drift);

    const dim3 blk(256);
    const dim3 gBig(2, BATCH / 128);    // BM=128, BN=128, N=256
    const dim3 gDual(4, BATCH / 128);   // dual N=256 weight sets
    const dim3 gLat(2, BATCH / 64);     // BM=64, BN=64, N=128
    const dim3 gSm(1, BATCH / 64);      // BM=64, BN=64, N=64

    const float* NP = nullptr;
    float* NPo = nullptr;

    // ---------------- encoder ----------------
    gemm_k<8, 4, EPI_SWISH, false><<<gBig, blk>>>(x, HID, HID, W_in, HID, b_in, bufA, HID,
                                                  NP, NP, NP, 0, NP, NP, NP, NPo, NP, NP, NP, NPo);
    for (int i = 0; i < NBLOCKS; ++i) {
        gemm_k<8, 4, EPI_SWISH, false><<<gBig, blk>>>(bufA, HID, HID,
                                                      Wb1 + (size_t)i * HID * HID, HID,
                                                      bb1 + (size_t)i * HID, bufB, HID,
                                                      NP, NP, NP, 0, NP, NP, NP, NPo, NP, NP, NP, NPo);
        gemm_k<8, 4, EPI_RES, false><<<gBig, blk>>>(bufB, HID, HID,
                                                    Wb2 + (size_t)i * HID * HID, HID,
                                                    bb2 + (size_t)i * HID, bufA, HID,
                                                    bufA, NP, NP, 0, NP, NP, NP, NPo, NP, NP, NP, NPo);
    }
    gemm_k<8, 4, EPI_NONE, false><<<gBig, blk>>>(bufA, HID, HID, W_fo, HID, b_fo, bufB, HID,
                                                 NP, NP, NP, 0, NP, NP, NP, NPo, NP, NP, NP, NPo);
    gemm_k<4, 2, EPI_LATENT, false><<<gLat, blk>>>(bufB, HID, HID, W_lat, 2 * LAT, b_lat, out_mu, LAT,
                                                   NP, NP, NP, 0, NP, NP, NP, out_s, NP, NP, NP, NPo);
    gemm_k<4, 2, EPI_Z0, false><<<gSm, blk>>>(bufB, HID, HID, W_init, LAT, b_init, z, LAT,
                                              NP, NP, NP, 0, NP, NP, NP, out_zp, NP, NP, NP, NPo);

    // ---------------- SDE integration (4 launches / step) ----------------
    // tz @ W = z @ W[1:] + t*W[0]  -> t-column folded into epilogue
    for (int s = 0; s < NSTEPS; ++s) {
        // drift hidden1 (-> bufA) and diffusion hidden1 (-> bufC), fused dual launch
        gemm_k<8, 4, EPI_TSWISH, true><<<gDual, blk>>>(z, LAT, LAT, Wd1 + HID, HID, bd1, bufA, HID,
                                                       NP, Wd1, ts, s, NP, NP, NP, NPo,
                                                       Wg1 + HID, bg1, Wg1, bufC);
        // drift hidden2
        gemm_k<8, 4, EPI_SWISH, false><<<gBig, blk>>>(bufA, HID, HID, Wd2, HID, bd2, bufB, HID,
                                                      NP, NP, NP, 0, NP, NP, NP, NPo, NP, NP, NP, NPo);
        // drift out
        gemm_k<4, 2, EPI_NONE, false><<<gSm, blk>>>(bufB, HID, HID, Wd3, LAT, bd3, drift, LAT,
                                                    NP, NP, NP, 0, NP, NP, NP, NPo, NP, NP, NP, NPo);
        // diffusion out + fused Euler-Maruyama update + z_path write
        gemm_k<4, 2, EPI_UPDATE, false><<<gSm, blk>>>(bufC, HID, HID, Wg2, LAT, bg2, z, LAT,
                                                      NP, NP, ts, s,
                                                      noise + (size_t)s * BATCH * LAT,
                                                      z, drift,
                                                      out_zp + (size_t)(s + 1) * BATCH * LAT,
                                                      NP, NP, NP, NPo);
    }
}

// round 12
// speedup vs baseline: 1.4238x; 1.1752x over previous
#include <cuda_runtime.h>
#include <cuda_bf16.h>
#include <math.h>

#define BATCH   16384
#define HID     256
#define LAT     64
#define NBLOCKS 3
#define NSTEPS  63   // T-1

typedef unsigned long long ull;

// ---------------- scratch (static device globals; no runtime allocation) ----
__device__ float g_bufA[BATCH * HID];   // h1d
__device__ float g_bufB[BATCH * HID];   // h2
__device__ float g_bufC[BATCH * HID];   // h1g
__device__ float g_z[BATCH * LAT];
__device__ float g_gout[BATCH * LAT];

// ---------------- packed f32x2 helpers (Blackwell FFMA2 path) --------------
__device__ __forceinline__ ull pack2(float x, float y) {
    ull r;
    asm("mov.b64 %0, {%1, %2};" : "=l"(r) : "f"(x), "f"(y));
    return r;
}
__device__ __forceinline__ void unpack2(ull v, float& x, float& y) {
    asm("mov.b64 {%0, %1}, %2;" : "=f"(x), "=f"(y) : "l"(v));
}
__device__ __forceinline__ void ffma2(ull& d, ull a, ull b) {
    asm("fma.rn.f32x2 %0, %1, %2, %0;" : "+l"(d) : "l"(a), "l"(b));
}

__device__ __forceinline__ float swish_f(float x) {
    return x / (1.0f + expf(-x));
}
__device__ __forceinline__ float softplus_f(float x) {
    return fmaxf(x, 0.0f) + log1pf(expf(-fabsf(x)));
}

#define CLUSTER_SYNC() do { \
    asm volatile("barrier.cluster.arrive.aligned;" ::: "memory"); \
    asm volatile("barrier.cluster.wait.aligned;"   ::: "memory"); \
} while (0)

// ---------------- epilogue codes (encoder kernels) -------------------------
constexpr int EPI_NONE   = 0;
constexpr int EPI_SWISH  = 1;
constexpr int EPI_RES    = 2;
constexpr int EPI_LATENT = 4;
constexpr int EPI_Z0     = 5;

template <int EPI>
__device__ __forceinline__ void epi_elem(
    float v, int r, int c,
    const float* __restrict__ bias,
    const float* __restrict__ res,
    float* __restrict__ C, int ldc,
    float* __restrict__ out2)
{
    float xv = v + bias[c];
    if constexpr (EPI == EPI_NONE) {
        C[(size_t)r * ldc + c] = xv;
    } else if constexpr (EPI == EPI_SWISH) {
        C[(size_t)r * ldc + c] = swish_f(xv);
    } else if constexpr (EPI == EPI_RES) {
        C[(size_t)r * ldc + c] = xv + res[(size_t)r * ldc + c];
    } else if constexpr (EPI == EPI_LATENT) {
        if (c < LAT) C[(size_t)r * LAT + c] = xv;
        else         out2[(size_t)r * LAT + (c - LAT)] = expf(0.5f * xv);
    } else if constexpr (EPI == EPI_Z0) {
        size_t idx = (size_t)r * LAT + c;
        C[idx] = xv;
        out2[idx] = xv;
    }
}

// ---------------- encoder GEMM (same machinery as R7) ----------------------
template <int TM, int NB, int EPI>
__global__ __launch_bounds__(256, 2)
void gemm_k(const float* __restrict__ A, int lda, int K,
            const float* __restrict__ W, int ldw,
            const float* __restrict__ bias,
            float* __restrict__ C, int ldc,
            const float* __restrict__ res,
            float* __restrict__ out2)
{
    constexpr int BK = 8;
    constexpr int BM = 16 * TM;
    constexpr int BN = 32 * NB;
    constexpr int TN = 2 * NB;

    __shared__ __align__(16) float As[2][BK][BM + 4];
    __shared__ __align__(16) ull   Ws2[2][BK][BN];

    const int tid = threadIdx.x;
    const int tx  = tid & 15;
    const int ty  = tid >> 4;
    const int row0 = blockIdx.y * BM;
    const int col0 = blockIdx.x * BN;

    const bool a_act = (tid < 2 * BM);
    const int a_row = tid >> 1;
    const int a_kc  = (tid & 1) * 4;
    const float* Ap = A + (size_t)(row0 + a_row) * lda + a_kc;

    const int w_r  = tid >> 5;
    const int w_c0 = tid & 31;
    const float* Wp = W + (size_t)w_r * ldw + col0 + w_c0;

    float4 ra;
    float  rw[NB];

    if (a_act) ra = *reinterpret_cast<const float4*>(Ap);
#pragma unroll
    for (int i = 0; i < NB; ++i) rw[i] = Wp[32 * i];

    if (a_act) {
        As[0][a_kc + 0][a_row] = ra.x;
        As[0][a_kc + 1][a_row] = ra.y;
        As[0][a_kc + 2][a_row] = ra.z;
        As[0][a_kc + 3][a_row] = ra.w;
    }
#pragma unroll
    for (int i = 0; i < NB; ++i) Ws2[0][w_r][w_c0 + 32 * i] = pack2(rw[i], rw[i]);
    __syncthreads();

    ull acc[TM / 2][TN];
#pragma unroll
    for (int i = 0; i < TM / 2; ++i)
#pragma unroll
        for (int j = 0; j < TN; ++j) acc[i][j] = 0ull;

    const int nst = K / BK;
    for (int s = 0; s < nst; ++s) {
        const int buf = s & 1;
        const bool has_next = (s + 1 < nst);

        if (has_next) {
            const int k0 = (s + 1) * BK;
            if (a_act) ra = *reinterpret_cast<const float4*>(Ap + k0);
#pragma unroll
            for (int i = 0; i < NB; ++i) rw[i] = Wp[(size_t)k0 * ldw + 32 * i];
        }

#pragma unroll
        for (int kk = 0; kk < BK; ++kk) {
            ull areg[TM / 2];
            ull breg[TN];
#pragma unroll
            for (int p = 0; p < TM / 4; ++p) {
                ulonglong2 t2 = *reinterpret_cast<const ulonglong2*>(
                    &As[buf][kk][ty * TM + 4 * p]);
                areg[2 * p]     = t2.x;
                areg[2 * p + 1] = t2.y;
            }
#pragma unroll
            for (int g = 0; g < NB; ++g) {
                ulonglong2 t2 = *reinterpret_cast<const ulonglong2*>(
                    &Ws2[buf][kk][2 * tx + 32 * g]);
                breg[2 * g]     = t2.x;
                breg[2 * g + 1] = t2.y;
            }
#pragma unroll
            for (int i = 0; i < TM / 2; ++i)
#pragma unroll
                for (int j = 0; j < TN; ++j)
                    ffma2(acc[i][j], areg[i], breg[j]);
        }

        if (has_next) {
            const int nb = buf ^ 1;
            if (a_act) {
                As[nb][a_kc + 0][a_row] = ra.x;
                As[nb][a_kc + 1][a_row] = ra.y;
                As[nb][a_kc + 2][a_row] = ra.z;
                As[nb][a_kc + 3][a_row] = ra.w;
            }
#pragma unroll
            for (int i = 0; i < NB; ++i) Ws2[nb][w_r][w_c0 + 32 * i] = pack2(rw[i], rw[i]);
            __syncthreads();
        }
    }

    const int rb = row0 + ty * TM;
#pragma unroll
    for (int i = 0; i < TM / 2; ++i) {
#pragma unroll
        for (int j = 0; j < TN; ++j) {
            float vx, vy;
            unpack2(acc[i][j], vx, vy);
            const int c = col0 + 2 * tx + 32 * (j >> 1) + (j & 1);
            epi_elem<EPI>(vx, rb + 2 * i,     c, bias, res, C, ldc, out2);
            epi_elem<EPI>(vy, rb + 2 * i + 1, c, bias, res, C, ldc, out2);
        }
    }
}

// ---------------- device-side GEMM tile for persistent SDE kernel ----------
// Fixed BM=128, BK=8, 256 threads. NB in {4,2} (BN=128/64). CG: __ldcg on A.
constexpr int P_BK = 8;
constexpr int P_BM = 128;
constexpr int AS_STR = P_BM + 4;   // floats
constexpr int WS_STR = 128;        // ull slots (max BN)

template <int NB, bool CG>
__device__ __forceinline__ void mm_tile(
    const float* __restrict__ A, int lda, int K,
    const float* __restrict__ W, int ldw,
    float* __restrict__ As, ull* __restrict__ Ws,
    ull (&acc)[4][2 * NB], int tid)
{
    constexpr int TN = 2 * NB;
    const int tx = tid & 15;
    const int ty = tid >> 4;
    const int a_row = tid >> 1;
    const int a_kc  = (tid & 1) * 4;
    const float* Ap = A + (size_t)a_row * lda + a_kc;
    const int w_r  = tid >> 5;
    const int w_c0 = tid & 31;
    const float* Wp = W + (size_t)w_r * ldw + w_c0;

#pragma unroll
    for (int i = 0; i < 4; ++i)
#pragma unroll
        for (int j = 0; j < TN; ++j) acc[i][j] = 0ull;

    float4 ra;
    float  rw[NB];

    if (CG) ra = __ldcg(reinterpret_cast<const float4*>(Ap));
    else    ra = *reinterpret_cast<const float4*>(Ap);
#pragma unroll
    for (int i = 0; i < NB; ++i) rw[i] = Wp[32 * i];

    As[(0 * P_BK + a_kc + 0) * AS_STR + a_row] = ra.x;
    As[(0 * P_BK + a_kc + 1) * AS_STR + a_row] = ra.y;
    As[(0 * P_BK + a_kc + 2) * AS_STR + a_row] = ra.z;
    As[(0 * P_BK + a_kc + 3) * AS_STR + a_row] = ra.w;
#pragma unroll
    for (int i = 0; i < NB; ++i)
        Ws[(0 * P_BK + w_r) * WS_STR + w_c0 + 32 * i] = pack2(rw[i], rw[i]);
    __syncthreads();

    const int nst = K / P_BK;
    for (int s = 0; s < nst; ++s) {
        const int buf = s & 1;
        const bool has_next = (s + 1 < nst);

        if (has_next) {
            const int k0 = (s + 1) * P_BK;
            if (CG) ra = __ldcg(reinterpret_cast<const float4*>(Ap + k0));
            else    ra = *reinterpret_cast<const float4*>(Ap + k0);
#pragma unroll
            for (int i = 0; i < NB; ++i) rw[i] = Wp[(size_t)k0 * ldw + 32 * i];
        }

#pragma unroll
        for (int kk = 0; kk < P_BK; ++kk) {
            ull areg[4];
            ull breg[TN];
#pragma unroll
            for (int p = 0; p < 2; ++p) {
                ulonglong2 t2 = *reinterpret_cast<const ulonglong2*>(
                    &As[(buf * P_BK + kk) * AS_STR + ty * 8 + 4 * p]);
                areg[2 * p]     = t2.x;
                areg[2 * p + 1] = t2.y;
            }
#pragma unroll
            for (int g = 0; g < NB; ++g) {
                ulonglong2 t2 = *reinterpret_cast<const ulonglong2*>(
                    &Ws[(buf * P_BK + kk) * WS_STR + 2 * tx + 32 * g]);
                breg[2 * g]     = t2.x;
                breg[2 * g + 1] = t2.y;
            }
#pragma unroll
            for (int i = 0; i < 4; ++i)
#pragma unroll
                for (int j = 0; j < TN; ++j)
                    ffma2(acc[i][j], areg[i], breg[j]);
        }

        if (has_next) {
            const int nb = buf ^ 1;
            As[(nb * P_BK + a_kc + 0) * AS_STR + a_row] = ra.x;
            As[(nb * P_BK + a_kc + 1) * AS_STR + a_row] = ra.y;
            As[(nb * P_BK + a_kc + 2) * AS_STR + a_row] = ra.z;
            As[(nb * P_BK + a_kc + 3) * AS_STR + a_row] = ra.w;
#pragma unroll
            for (int i = 0; i < NB; ++i)
                Ws[(nb * P_BK + w_r) * WS_STR + w_c0 + 32 * i] = pack2(rw[i], rw[i]);
            __syncthreads();
        }
    }
    __syncthreads();   // smem reusable by next phase
}

__device__ __forceinline__ int acc_col(int tx, int j) {
    return 2 * tx + 32 * (j >> 1) + (j & 1);
}

// ---------------- persistent fused SDE kernel -------------------------------
// Cluster of 2 CTAs per 128-row block: rank = col-half owner.
// All 63 Euler-Maruyama steps in one launch; activations via L2-resident
// global scratch; 4 cluster syncs per step.
__global__ __launch_bounds__(256, 2) __cluster_dims__(2, 1, 1)
void sde_kernel(const float* __restrict__ ts,
                const float* __restrict__ noise,
                const float* __restrict__ Wd1, const float* __restrict__ bd1,
                const float* __restrict__ Wd2, const float* __restrict__ bd2,
                const float* __restrict__ Wd3, const float* __restrict__ bd3,
                const float* __restrict__ Wg1, const float* __restrict__ bg1,
                const float* __restrict__ Wg2, const float* __restrict__ bg2,
                float* __restrict__ out_zp)
{
    __shared__ __align__(16) float As[2 * P_BK * AS_STR];
    __shared__ __align__(16) ull   Ws[2 * P_BK * WS_STR];

    const int tid  = threadIdx.x;
    const int tx   = tid & 15;
    const int ty   = tid >> 4;
    const int rank = blockIdx.x;          // 0/1 within cluster
    const int rb   = blockIdx.y;          // row block (128 rows)
    const int col0 = rank * 128;

    float* zS  = g_z    + (size_t)rb * 128 * LAT;
    float* h1d = g_bufA + (size_t)rb * 128 * HID;
    float* h1g = g_bufC + (size_t)rb * 128 * HID;
    float* h2S = g_bufB + (size_t)rb * 128 * HID;
    float* gsl = g_gout + (size_t)rb * 128 * LAT;

    for (int s = 0; s < NSTEPS; ++s) {
        const float t  = ts[s];
        const float dt = ts[s + 1] - t;
        const float sd = sqrtf(dt);

        CLUSTER_SYNC();   // z (and scratch buffers) ready for this step

        // ---- phase 1: h1d / h1g col-halves;  tz@W = z@W[1:] + t*W[0] ----
        {
            ull acc[4][8];
            mm_tile<4, true>(zS, LAT, LAT, Wd1 + HID + col0, HID, As, Ws, acc, tid);
#pragma unroll
            for (int i = 0; i < 4; ++i)
#pragma unroll
                for (int j = 0; j < 8; ++j) {
                    float vx, vy;
                    unpack2(acc[i][j], vx, vy);
                    const int c = col0 + acc_col(tx, j);
                    const int r = ty * 8 + 2 * i;
                    const float bb = bd1[c] + t * Wd1[c];
                    h1d[(size_t)r * HID + c]       = swish_f(vx + bb);
                    h1d[(size_t)(r + 1) * HID + c] = swish_f(vy + bb);
                }
            mm_tile<4, true>(zS, LAT, LAT, Wg1 + HID + col0, HID, As, Ws, acc, tid);
#pragma unroll
            for (int i = 0; i < 4; ++i)
#pragma unroll
                for (int j = 0; j < 8; ++j) {
                    float vx, vy;
                    unpack2(acc[i][j], vx, vy);
                    const int c = col0 + acc_col(tx, j);
                    const int r = ty * 8 + 2 * i;
                    const float bb = bg1[c] + t * Wg1[c];
                    h1g[(size_t)r * HID + c]       = swish_f(vx + bb);
                    h1g[(size_t)(r + 1) * HID + c] = swish_f(vy + bb);
                }
        }
        CLUSTER_SYNC();   // h1 complete (both halves)

        // ---- phase 2: h2 col-half = swish(h1d @ Wd2 + bd2) ----
        {
            ull acc[4][8];
            mm_tile<4, true>(h1d, HID, HID, Wd2 + col0, HID, As, Ws, acc, tid);
#pragma unroll
            for (int i = 0; i < 4; ++i)
#pragma unroll
                for (int j = 0; j < 8; ++j) {
                    float vx, vy;
                    unpack2(acc[i][j], vx, vy);
                    const int c = col0 + acc_col(tx, j);
                    const int r = ty * 8 + 2 * i;
                    h2S[(size_t)r * HID + c]       = swish_f(vx + bd2[c]);
                    h2S[(size_t)(r + 1) * HID + c] = swish_f(vy + bd2[c]);
                }
        }
        CLUSTER_SYNC();   // h2 complete

        // ---- phase 3: rank0 -> drift (kept in regs); rank1 -> softplus(gout) ----
        if (rank == 0) {
            ull acc[4][4];
            mm_tile<2, true>(h2S, HID, HID, Wd3, LAT, As, Ws, acc, tid);
            CLUSTER_SYNC();   // gout ready from rank1

            // fused Euler-Maruyama update + z_path write
            const float* nz = noise + (size_t)s * BATCH * LAT + (size_t)rb * 128 * LAT;
            float* zp = out_zp + (size_t)(s + 1) * BATCH * LAT + (size_t)rb * 128 * LAT;
#pragma unroll
            for (int i = 0; i < 4; ++i)
#pragma unroll
                for (int j = 0; j < 4; ++j) {
                    float vx, vy;
                    unpack2(acc[i][j], vx, vy);
                    const int c = acc_col(tx, j);
                    const int r = ty * 8 + 2 * i;
                    {
                        const size_t idx = (size_t)r * LAT + c;
                        float dr = vx + bd3[c];
                        float zn = zS[idx] + dr * dt + __ldcg(&gsl[idx]) * sd * nz[idx];
                        zS[idx] = zn;
                        zp[idx] = zn;
                    }
                    {
                        const size_t idx = (size_t)(r + 1) * LAT + c;
                        float dr = vy + bd3[c];
                        float zn = zS[idx] + dr * dt + __ldcg(&gsl[idx]) * sd * nz[idx];
                        zS[idx] = zn;
                        zp[idx] = zn;
                    }
                }
        } else {
            ull acc[4][4];
            mm_tile<2, true>(h1g, HID, HID, Wg2, LAT, As, Ws, acc, tid);
#pragma unroll
            for (int i = 0; i < 4; ++i)
#pragma unroll
                for (int j = 0; j < 4; ++j) {
                    float vx, vy;
                    unpack2(acc[i][j], vx, vy);
                    const int c = acc_col(tx, j);
                    const int r = ty * 8 + 2 * i;
                    gsl[(size_t)r * LAT + c]       = softplus_f(vx + bg2[c]);
                    gsl[(size_t)(r + 1) * LAT + c] = softplus_f(vy + bg2[c]);
                }
            CLUSTER_SYNC();   // matches rank0's sync before update
        }
    }
}

// ---------------- host driver ----------------------------------------------
extern "C" void kernel_launch(void* const* d_in, const int* in_sizes, int n_in,
                              void* d_out, int out_size)
{
    (void)in_sizes; (void)n_in; (void)out_size;

    const float* x      = (const float*)d_in[0];
    const float* ts     = (const float*)d_in[1];
    const float* noise  = (const float*)d_in[2];
    const float* W_in   = (const float*)d_in[3];
    const float* b_in   = (const float*)d_in[4];
    const float* Wb1    = (const float*)d_in[5];
    const float* bb1    = (const float*)d_in[6];
    const float* Wb2    = (const float*)d_in[7];
    const float* bb2    = (const float*)d_in[8];
    const float* W_fo   = (const float*)d_in[9];
    const float* b_fo   = (const float*)d_in[10];
    const float* W_lat  = (const float*)d_in[11];
    const float* b_lat  = (const float*)d_in[12];
    const float* W_init = (const float*)d_in[13];
    const float* b_init = (const float*)d_in[14];
    const float* Wd1    = (const float*)d_in[15];
    const float* bd1    = (const float*)d_in[16];
    const float* Wd2    = (const float*)d_in[17];
    const float* bd2    = (const float*)d_in[18];
    const float* Wd3    = (const float*)d_in[19];
    const float* bd3    = (const float*)d_in[20];
    const float* Wg1    = (const float*)d_in[21];
    const float* bg1    = (const float*)d_in[22];
    const float* Wg2    = (const float*)d_in[23];
    const float* bg2    = (const float*)d_in[24];

    float* out    = (float*)d_out;
    float* out_mu = out;
    float* out_s  = out + (size_t)BATCH * LAT;
    float* out_zp = out + (size_t)2 * BATCH * LAT;   // z_path[t]

    float *bufA, *bufB, *z;
    cudaGetSymbolAddress((void**)&bufA, g_bufA);
    cudaGetSymbolAddress((void**)&bufB, g_bufB);
    cudaGetSymbolAddress((void**)&z,    g_z);

    const dim3 blk(256);
    const dim3 gBig(2, BATCH / 128);    // BM=128, BN=128, N=256
    const dim3 gLat(2, BATCH / 64);     // BM=64,  BN=64,  N=128
    const dim3 gSm(1, BATCH / 64);      // BM=64,  BN=64,  N=64

    const float* NP = nullptr;
    float* NPo = nullptr;

    // ---------------- encoder ----------------
    gemm_k<8, 4, EPI_SWISH><<<gBig, blk>>>(x, HID, HID, W_in, HID, b_in, bufA, HID, NP, NPo);
    for (int i = 0; i < NBLOCKS; ++i) {
        gemm_k<8, 4, EPI_SWISH><<<gBig, blk>>>(bufA, HID, HID,
                                               Wb1 + (size_t)i * HID * HID, HID,
                                               bb1 + (size_t)i * HID, bufB, HID, NP, NPo);
        gemm_k<8, 4, EPI_RES><<<gBig, blk>>>(bufB, HID, HID,
                                             Wb2 + (size_t)i * HID * HID, HID,
                                             bb2 + (size_t)i * HID, bufA, HID, bufA, NPo);
    }
    gemm_k<8, 4, EPI_NONE><<<gBig, blk>>>(bufA, HID, HID, W_fo, HID, b_fo, bufB, HID, NP, NPo);
    gemm_k<4, 2, EPI_LATENT><<<gLat, blk>>>(bufB, HID, HID, W_lat, 2 * LAT, b_lat,
                                            out_mu, LAT, NP, out_s);
    gemm_k<4, 2, EPI_Z0><<<gSm, blk>>>(bufB, HID, HID, W_init, LAT, b_init,
                                       z, LAT, NP, out_zp);

    // ---------------- SDE integration: ONE persistent clustered launch ------
    const dim3 gSde(2, BATCH / 128);    // 128 clusters of 2 CTAs
    sde_kernel<<<gSde, blk>>>(ts, noise,
                              Wd1, bd1, Wd2, bd2, Wd3, bd3,
                              Wg1, bg1, Wg2, bg2, out_zp);
}

// round 14
// speedup vs baseline: 1.4736x; 1.0350x over previous
#include <cuda_runtime.h>
#include <cuda_bf16.h>
#include <math.h>

#define BATCH   16384
#define HID     256
#define LAT     64
#define NBLOCKS 3
#define NSTEPS  63   // T-1

typedef unsigned long long ull;

// ---------------- scratch (static device globals; no runtime allocation) ----
__device__ float g_bufA[BATCH * HID];   // h1d
__device__ float g_bufB[BATCH * HID];   // h2
__device__ float g_bufC[BATCH * HID];   // h1g
__device__ float g_z[BATCH * LAT];
__device__ float g_gout[BATCH * LAT];

// ---------------- packed f32x2 helpers (Blackwell FFMA2 path) --------------
__device__ __forceinline__ ull pack2(float x, float y) {
    ull r;
    asm("mov.b64 %0, {%1, %2};" : "=l"(r) : "f"(x), "f"(y));
    return r;
}
__device__ __forceinline__ void unpack2(ull v, float& x, float& y) {
    asm("mov.b64 {%0, %1}, %2;" : "=f"(x), "=f"(y) : "l"(v));
}
__device__ __forceinline__ void ffma2(ull& d, ull a, ull b) {
    asm("fma.rn.f32x2 %0, %1, %2, %0;" : "+l"(d) : "l"(a), "l"(b));
}

__device__ __forceinline__ float swish_f(float x) {
    return x / (1.0f + expf(-x));
}
__device__ __forceinline__ float softplus_f(float x) {
    return fmaxf(x, 0.0f) + log1pf(expf(-fabsf(x)));
}

// ---------------- epilogue codes (encoder kernels) -------------------------
constexpr int EPI_NONE   = 0;
constexpr int EPI_SWISH  = 1;
constexpr int EPI_RES    = 2;
constexpr int EPI_LATENT = 4;
constexpr int EPI_Z0     = 5;

template <int EPI>
__device__ __forceinline__ void epi_elem(
    float v, int r, int c,
    const float* __restrict__ bias,
    const float* __restrict__ res,
    float* __restrict__ C, int ldc,
    float* __restrict__ out2)
{
    float xv = v + bias[c];
    if constexpr (EPI == EPI_NONE) {
        C[(size_t)r * ldc + c] = xv;
    } else if constexpr (EPI == EPI_SWISH) {
        C[(size_t)r * ldc + c] = swish_f(xv);
    } else if constexpr (EPI == EPI_RES) {
        C[(size_t)r * ldc + c] = xv + res[(size_t)r * ldc + c];
    } else if constexpr (EPI == EPI_LATENT) {
        if (c < LAT) C[(size_t)r * LAT + c] = xv;
        else         out2[(size_t)r * LAT + (c - LAT)] = expf(0.5f * xv);
    } else if constexpr (EPI == EPI_Z0) {
        size_t idx = (size_t)r * LAT + c;
        C[idx] = xv;
        out2[idx] = xv;
    }
}

// ---------------- encoder GEMM (unchanged from R11) ------------------------
template <int TM, int NB, int EPI>
__global__ __launch_bounds__(256, 2)
void gemm_k(const float* __restrict__ A, int lda, int K,
            const float* __restrict__ W, int ldw,
            const float* __restrict__ bias,
            float* __restrict__ C, int ldc,
            const float* __restrict__ res,
            float* __restrict__ out2)
{
    constexpr int BK = 8;
    constexpr int BM = 16 * TM;
    constexpr int BN = 32 * NB;
    constexpr int TN = 2 * NB;

    __shared__ __align__(16) float As[2][BK][BM + 4];
    __shared__ __align__(16) ull   Ws2[2][BK][BN];

    const int tid = threadIdx.x;
    const int tx  = tid & 15;
    const int ty  = tid >> 4;
    const int row0 = blockIdx.y * BM;
    const int col0 = blockIdx.x * BN;

    const bool a_act = (tid < 2 * BM);
    const int a_row = tid >> 1;
    const int a_kc  = (tid & 1) * 4;
    const float* Ap = A + (size_t)(row0 + a_row) * lda + a_kc;

    const int w_r  = tid >> 5;
    const int w_c0 = tid & 31;
    const float* Wp = W + (size_t)w_r * ldw + col0 + w_c0;

    float4 ra;
    float  rw[NB];

    if (a_act) ra = *reinterpret_cast<const float4*>(Ap);
#pragma unroll
    for (int i = 0; i < NB; ++i) rw[i] = Wp[32 * i];

    if (a_act) {
        As[0][a_kc + 0][a_row] = ra.x;
        As[0][a_kc + 1][a_row] = ra.y;
        As[0][a_kc + 2][a_row] = ra.z;
        As[0][a_kc + 3][a_row] = ra.w;
    }
#pragma unroll
    for (int i = 0; i < NB; ++i) Ws2[0][w_r][w_c0 + 32 * i] = pack2(rw[i], rw[i]);
    __syncthreads();

    ull acc[TM / 2][TN];
#pragma unroll
    for (int i = 0; i < TM / 2; ++i)
#pragma unroll
        for (int j = 0; j < TN; ++j) acc[i][j] = 0ull;

    const int nst = K / BK;
    for (int s = 0; s < nst; ++s) {
        const int buf = s & 1;
        const bool has_next = (s + 1 < nst);

        if (has_next) {
            const int k0 = (s + 1) * BK;
            if (a_act) ra = *reinterpret_cast<const float4*>(Ap + k0);
#pragma unroll
            for (int i = 0; i < NB; ++i) rw[i] = Wp[(size_t)k0 * ldw + 32 * i];
        }

#pragma unroll
        for (int kk = 0; kk < BK; ++kk) {
            ull areg[TM / 2];
            ull breg[TN];
#pragma unroll
            for (int p = 0; p < TM / 4; ++p) {
                ulonglong2 t2 = *reinterpret_cast<const ulonglong2*>(
                    &As[buf][kk][ty * TM + 4 * p]);
                areg[2 * p]     = t2.x;
                areg[2 * p + 1] = t2.y;
            }
#pragma unroll
            for (int g = 0; g < NB; ++g) {
                ulonglong2 t2 = *reinterpret_cast<const ulonglong2*>(
                    &Ws2[buf][kk][2 * tx + 32 * g]);
                breg[2 * g]     = t2.x;
                breg[2 * g + 1] = t2.y;
            }
#pragma unroll
            for (int i = 0; i < TM / 2; ++i)
#pragma unroll
                for (int j = 0; j < TN; ++j)
                    ffma2(acc[i][j], areg[i], breg[j]);
        }

        if (has_next) {
            const int nb = buf ^ 1;
            if (a_act) {
                As[nb][a_kc + 0][a_row] = ra.x;
                As[nb][a_kc + 1][a_row] = ra.y;
                As[nb][a_kc + 2][a_row] = ra.z;
                As[nb][a_kc + 3][a_row] = ra.w;
            }
#pragma unroll
            for (int i = 0; i < NB; ++i) Ws2[nb][w_r][w_c0 + 32 * i] = pack2(rw[i], rw[i]);
            __syncthreads();
        }
    }

    const int rb = row0 + ty * TM;
#pragma unroll
    for (int i = 0; i < TM / 2; ++i) {
#pragma unroll
        for (int j = 0; j < TN; ++j) {
            float vx, vy;
            unpack2(acc[i][j], vx, vy);
            const int c = col0 + 2 * tx + 32 * (j >> 1) + (j & 1);
            epi_elem<EPI>(vx, rb + 2 * i,     c, bias, res, C, ldc, out2);
            epi_elem<EPI>(vy, rb + 2 * i + 1, c, bias, res, C, ldc, out2);
        }
    }
}

// ---------------- SDE persistent-kernel building blocks --------------------
constexpr int P_BK   = 8;
constexpr int AS_STR = 132;   // floats per k-plane (128 + 4 pad)
constexpr int WS_STR = 128;   // ull slots per k-plane

// GEMM tile with A from GLOBAL (ldcg) — BM=128, 256-thread half, NB in {4,2}.
template <int NB>
__device__ __forceinline__ void mm_tile_g(
    const float* __restrict__ A, int lda, int K,
    const float* __restrict__ W, int ldw,
    float* __restrict__ As, ull* __restrict__ Ws,
    ull (&acc)[4][2 * NB], int t2)
{
    constexpr int TN = 2 * NB;
    const int tx = t2 & 15;
    const int ty = t2 >> 4;
    const int a_row = t2 >> 1;
    const int a_kc  = (t2 & 1) * 4;
    const float* Ap = A + (size_t)a_row * lda + a_kc;
    const int w_r  = t2 >> 5;
    const int w_c0 = t2 & 31;
    const float* Wp = W + (size_t)w_r * ldw + w_c0;

#pragma unroll
    for (int i = 0; i < 4; ++i)
#pragma unroll
        for (int j = 0; j < TN; ++j) acc[i][j] = 0ull;

    float4 ra = __ldcg(reinterpret_cast<const float4*>(Ap));
    float  rw[NB];
#pragma unroll
    for (int i = 0; i < NB; ++i) rw[i] = Wp[32 * i];

    As[(a_kc + 0) * AS_STR + a_row] = ra.x;
    As[(a_kc + 1) * AS_STR + a_row] = ra.y;
    As[(a_kc + 2) * AS_STR + a_row] = ra.z;
    As[(a_kc + 3) * AS_STR + a_row] = ra.w;
#pragma unroll
    for (int i = 0; i < NB; ++i)
        Ws[w_r * WS_STR + w_c0 + 32 * i] = pack2(rw[i], rw[i]);
    __syncthreads();

    const int nst = K / P_BK;
    for (int s = 0; s < nst; ++s) {
        const int buf = s & 1;
        const bool has_next = (s + 1 < nst);

        if (has_next) {
            const int k0 = (s + 1) * P_BK;
            ra = __ldcg(reinterpret_cast<const float4*>(Ap + k0));
#pragma unroll
            for (int i = 0; i < NB; ++i) rw[i] = Wp[(size_t)k0 * ldw + 32 * i];
        }

#pragma unroll
        for (int kk = 0; kk < P_BK; ++kk) {
            ull areg[4];
            ull breg[TN];
#pragma unroll
            for (int p = 0; p < 2; ++p) {
                ulonglong2 t2v = *reinterpret_cast<const ulonglong2*>(
                    &As[(buf * P_BK + kk) * AS_STR + ty * 8 + 4 * p]);
                areg[2 * p]     = t2v.x;
                areg[2 * p + 1] = t2v.y;
            }
#pragma unroll
            for (int g = 0; g < NB; ++g) {
                ulonglong2 t2v = *reinterpret_cast<const ulonglong2*>(
                    &Ws[(buf * P_BK + kk) * WS_STR + 2 * tx + 32 * g]);
                breg[2 * g]     = t2v.x;
                breg[2 * g + 1] = t2v.y;
            }
#pragma unroll
            for (int i = 0; i < 4; ++i)
#pragma unroll
                for (int j = 0; j < TN; ++j)
                    ffma2(acc[i][j], areg[i], breg[j]);
        }

        if (has_next) {
            const int nb = buf ^ 1;
            As[(nb * P_BK + a_kc + 0) * AS_STR + a_row] = ra.x;
            As[(nb * P_BK + a_kc + 1) * AS_STR + a_row] = ra.y;
            As[(nb * P_BK + a_kc + 2) * AS_STR + a_row] = ra.z;
            As[(nb * P_BK + a_kc + 3) * AS_STR + a_row] = ra.w;
#pragma unroll
            for (int i = 0; i < NB; ++i)
                Ws[(nb * P_BK + w_r) * WS_STR + w_c0 + 32 * i] = pack2(rw[i], rw[i]);
            __syncthreads();
        }
    }
    __syncthreads();
}

// GEMM tile with A resident in SMEM (zT, k-major [64][AS_STR]) — K=64 fixed.
template <int NB>
__device__ __forceinline__ void mm_tile_z(
    const float* __restrict__ zsm,
    const float* __restrict__ W, int ldw,
    ull* __restrict__ Ws,
    ull (&acc)[4][2 * NB], int t2)
{
    constexpr int TN = 2 * NB;
    const int tx = t2 & 15;
    const int ty = t2 >> 4;
    const int w_r  = t2 >> 5;
    const int w_c0 = t2 & 31;
    const float* Wp = W + (size_t)w_r * ldw + w_c0;

#pragma unroll
    for (int i = 0; i < 4; ++i)
#pragma unroll
        for (int j = 0; j < TN; ++j) acc[i][j] = 0ull;

    float rw[NB];
#pragma unroll
    for (int i = 0; i < NB; ++i) rw[i] = Wp[32 * i];
#pragma unroll
    for (int i = 0; i < NB; ++i)
        Ws[w_r * WS_STR + w_c0 + 32 * i] = pack2(rw[i], rw[i]);
    __syncthreads();

    const int nst = LAT / P_BK;   // 8
    for (int s = 0; s < nst; ++s) {
        const int buf = s & 1;
        const bool has_next = (s + 1 < nst);

        if (has_next) {
            const int k0 = (s + 1) * P_BK;
#pragma unroll
            for (int i = 0; i < NB; ++i) rw[i] = Wp[(size_t)k0 * ldw + 32 * i];
        }

#pragma unroll
        for (int kk = 0; kk < P_BK; ++kk) {
            ull areg[4];
            ull breg[TN];
#pragma unroll
            for (int p = 0; p < 2; ++p) {
                ulonglong2 t2v = *reinterpret_cast<const ulonglong2*>(
                    &zsm[(s * P_BK + kk) * AS_STR + ty * 8 + 4 * p]);
                areg[2 * p]     = t2v.x;
                areg[2 * p + 1] = t2v.y;
            }
#pragma unroll
            for (int g = 0; g < NB; ++g) {
                ulonglong2 t2v = *reinterpret_cast<const ulonglong2*>(
                    &Ws[(buf * P_BK + kk) * WS_STR + 2 * tx + 32 * g]);
                breg[2 * g]     = t2v.x;
                breg[2 * g + 1] = t2v.y;
            }
#pragma unroll
            for (int i = 0; i < 4; ++i)
#pragma unroll
                for (int j = 0; j < TN; ++j)
                    ffma2(acc[i][j], areg[i], breg[j]);
        }

        if (has_next) {
            const int nb = buf ^ 1;
#pragma unroll
            for (int i = 0; i < NB; ++i)
                Ws[(nb * P_BK + w_r) * WS_STR + w_c0 + 32 * i] = pack2(rw[i], rw[i]);
            __syncthreads();
        }
    }
    __syncthreads();
}

// ---------------- persistent fused SDE kernel: ONE 512-thread CTA / 128 rows
// Two 256-thread halves own the two 128-col halves; all phase syncs are
// plain __syncthreads (no CCTL.IVALL -> weights stay L1-resident);
// z lives in SMEM (k-major) across all 63 steps.
constexpr int SDE_SMEM =
    (LAT * AS_STR) * 4 +                // zT
    2 * (2 * P_BK * AS_STR) * 4 +       // As per half
    2 * (2 * P_BK * WS_STR) * 8;        // Ws per half

__global__ __launch_bounds__(512, 1)
void sde_kernel(const float* __restrict__ ts,
                const float* __restrict__ noise,
                const float* __restrict__ Wd1, const float* __restrict__ bd1,
                const float* __restrict__ Wd2, const float* __restrict__ bd2,
                const float* __restrict__ Wd3, const float* __restrict__ bd3,
                const float* __restrict__ Wg1, const float* __restrict__ bg1,
                const float* __restrict__ Wg2, const float* __restrict__ bg2,
                float* __restrict__ out_zp)
{
    extern __shared__ __align__(16) char sm_raw[];
    float* zT     = reinterpret_cast<float*>(sm_raw);
    float* AsBase = zT + LAT * AS_STR;
    ull*   WsBase = reinterpret_cast<ull*>(AsBase + 2 * (2 * P_BK * AS_STR));

    const int tid  = threadIdx.x;
    const int half = tid >> 8;
    const int t2   = tid & 255;
    const int tx   = t2 & 15;
    const int ty   = t2 >> 4;
    const int rb   = blockIdx.x;
    const int col0 = half * 128;

    float* As = AsBase + half * (2 * P_BK * AS_STR);
    ull*   Ws = WsBase + half * (2 * P_BK * WS_STR);

    float* h1d = g_bufA + (size_t)rb * 128 * HID;
    float* h1g = g_bufC + (size_t)rb * 128 * HID;
    float* h2S = g_bufB + (size_t)rb * 128 * HID;
    float* gsl = g_gout + (size_t)rb * 128 * LAT;
    const float* z0 = g_z + (size_t)rb * 128 * LAT;

    // ---- load z0 into SMEM (k-major transposed) ----
    for (int i = tid; i < 128 * LAT; i += 512) {
        const int r = i >> 6;
        const int c = i & 63;
        zT[c * AS_STR + r] = __ldcg(&z0[i]);
    }
    __syncthreads();

    for (int s = 0; s < NSTEPS; ++s) {
        const float t  = ts[s];
        const float dt = ts[s + 1] - t;
        const float sd = sqrtf(dt);

        // ---- phase 1: h1d/h1g col-halves; tz@W = z@W[1:] + t*W[0] ----
        {
            ull acc[4][8];
            mm_tile_z<4>(zT, Wd1 + HID + col0, HID, Ws, acc, t2);
#pragma unroll
            for (int i = 0; i < 4; ++i) {
                const int r = ty * 8 + 2 * i;
#pragma unroll
                for (int g = 0; g < 4; ++g) {
                    float x0, y0, x1, y1;
                    unpack2(acc[i][2 * g],     x0, y0);
                    unpack2(acc[i][2 * g + 1], x1, y1);
                    const int c = col0 + 2 * tx + 32 * g;
                    const float b0 = bd1[c]     + t * Wd1[c];
                    const float b1 = bd1[c + 1] + t * Wd1[c + 1];
                    __stcg(reinterpret_cast<float2*>(&h1d[(size_t)r * HID + c]),
                           make_float2(swish_f(x0 + b0), swish_f(x1 + b1)));
                    __stcg(reinterpret_cast<float2*>(&h1d[(size_t)(r + 1) * HID + c]),
                           make_float2(swish_f(y0 + b0), swish_f(y1 + b1)));
                }
            }
            mm_tile_z<4>(zT, Wg1 + HID + col0, HID, Ws, acc, t2);
#pragma unroll
            for (int i = 0; i < 4; ++i) {
                const int r = ty * 8 + 2 * i;
#pragma unroll
                for (int g = 0; g < 4; ++g) {
                    float x0, y0, x1, y1;
                    unpack2(acc[i][2 * g],     x0, y0);
                    unpack2(acc[i][2 * g + 1], x1, y1);
                    const int c = col0 + 2 * tx + 32 * g;
                    const float b0 = bg1[c]     + t * Wg1[c];
                    const float b1 = bg1[c + 1] + t * Wg1[c + 1];
                    __stcg(reinterpret_cast<float2*>(&h1g[(size_t)r * HID + c]),
                           make_float2(swish_f(x0 + b0), swish_f(x1 + b1)));
                    __stcg(reinterpret_cast<float2*>(&h1g[(size_t)(r + 1) * HID + c]),
                           make_float2(swish_f(y0 + b0), swish_f(y1 + b1)));
                }
            }
        }
        __syncthreads();   // S1: h1 visible (both halves)

        // ---- phase 2: h2 col-half = swish(h1d @ Wd2 + bd2) ----
        {
            ull acc[4][8];
            mm_tile_g<4>(h1d, HID, HID, Wd2 + col0, HID, As, Ws, acc, t2);
#pragma unroll
            for (int i = 0; i < 4; ++i) {
                const int r = ty * 8 + 2 * i;
#pragma unroll
                for (int g = 0; g < 4; ++g) {
                    float x0, y0, x1, y1;
                    unpack2(acc[i][2 * g],     x0, y0);
                    unpack2(acc[i][2 * g + 1], x1, y1);
                    const int c = col0 + 2 * tx + 32 * g;
                    const float b0 = bd2[c];
                    const float b1 = bd2[c + 1];
                    __stcg(reinterpret_cast<float2*>(&h2S[(size_t)r * HID + c]),
                           make_float2(swish_f(x0 + b0), swish_f(x1 + b1)));
                    __stcg(reinterpret_cast<float2*>(&h2S[(size_t)(r + 1) * HID + c]),
                           make_float2(swish_f(y0 + b0), swish_f(y1 + b1)));
                }
            }
        }
        __syncthreads();   // S2: h2 visible

        // ---- phase 3: half0 -> drift (kept in regs); half1 -> softplus(gout)
        {
            ull acc[4][4];
            const float* A3 = half ? h1g : h2S;
            const float* W3 = half ? Wg2 : Wd3;
            mm_tile_g<2>(A3, HID, HID, W3, LAT, As, Ws, acc, t2);

            if (half == 1) {
#pragma unroll
                for (int i = 0; i < 4; ++i) {
                    const int r = ty * 8 + 2 * i;
#pragma unroll
                    for (int g = 0; g < 2; ++g) {
                        float x0, y0, x1, y1;
                        unpack2(acc[i][2 * g],     x0, y0);
                        unpack2(acc[i][2 * g + 1], x1, y1);
                        const int c = 2 * tx + 32 * g;
                        const float b0 = bg2[c];
                        const float b1 = bg2[c + 1];
                        __stcg(reinterpret_cast<float2*>(&gsl[(size_t)r * LAT + c]),
                               make_float2(softplus_f(x0 + b0), softplus_f(x1 + b1)));
                        __stcg(reinterpret_cast<float2*>(&gsl[(size_t)(r + 1) * LAT + c]),
                               make_float2(softplus_f(y0 + b0), softplus_f(y1 + b1)));
                    }
                }
            }
            __syncthreads();   // S3: gout visible

            // ---- update (half0): z += drift*dt + gout*sqrt(dt)*noise ----
            if (half == 0) {
                const float* nz = noise + (size_t)s * BATCH * LAT + (size_t)rb * 128 * LAT;
                float* zp = out_zp + (size_t)(s + 1) * BATCH * LAT + (size_t)rb * 128 * LAT;
#pragma unroll
                for (int i = 0; i < 4; ++i) {
#pragma unroll
                    for (int g = 0; g < 2; ++g) {
                        float x0, y0, x1, y1;
                        unpack2(acc[i][2 * g],     x0, y0);
                        unpack2(acc[i][2 * g + 1], x1, y1);
                        const int c = 2 * tx + 32 * g;
                        const int r = ty * 8 + 2 * i;
                        {
                            const size_t idx = (size_t)r * LAT + c;
                            const float2 gv = __ldcg(reinterpret_cast<const float2*>(&gsl[idx]));
                            const float2 nv = *reinterpret_cast<const float2*>(&nz[idx]);
                            float zn0 = zT[c * AS_STR + r]
                                      + (x0 + bd3[c]) * dt + gv.x * sd * nv.x;
                            float zn1 = zT[(c + 1) * AS_STR + r]
                                      + (x1 + bd3[c + 1]) * dt + gv.y * sd * nv.y;
                            zT[c * AS_STR + r]       = zn0;
                            zT[(c + 1) * AS_STR + r] = zn1;
                            *reinterpret_cast<float2*>(&zp[idx]) = make_float2(zn0, zn1);
                        }
                        {
                            const size_t idx = (size_t)(r + 1) * LAT + c;
                            const float2 gv = __ldcg(reinterpret_cast<const float2*>(&gsl[idx]));
                            const float2 nv = *reinterpret_cast<const float2*>(&nz[idx]);
                            float zn0 = zT[c * AS_STR + r + 1]
                                      + (y0 + bd3[c]) * dt + gv.x * sd * nv.x;
                            float zn1 = zT[(c + 1) * AS_STR + r + 1]
                                      + (y1 + bd3[c + 1]) * dt + gv.y * sd * nv.y;
                            zT[c * AS_STR + r + 1]       = zn0;
                            zT[(c + 1) * AS_STR + r + 1] = zn1;
                            *reinterpret_cast<float2*>(&zp[idx]) = make_float2(zn0, zn1);
                        }
                    }
                }
            }
        }
        __syncthreads();   // S4: zT ready for next step's phase 1
    }
}

// ---------------- host driver ----------------------------------------------
extern "C" void kernel_launch(void* const* d_in, const int* in_sizes, int n_in,
                              void* d_out, int out_size)
{
    (void)in_sizes; (void)n_in; (void)out_size;

    const float* x      = (const float*)d_in[0];
    const float* ts     = (const float*)d_in[1];
    const float* noise  = (const float*)d_in[2];
    const float* W_in   = (const float*)d_in[3];
    const float* b_in   = (const float*)d_in[4];
    const float* Wb1    = (const float*)d_in[5];
    const float* bb1    = (const float*)d_in[6];
    const float* Wb2    = (const float*)d_in[7];
    const float* bb2    = (const float*)d_in[8];
    const float* W_fo   = (const float*)d_in[9];
    const float* b_fo   = (const float*)d_in[10];
    const float* W_lat  = (const float*)d_in[11];
    const float* b_lat  = (const float*)d_in[12];
    const float* W_init = (const float*)d_in[13];
    const float* b_init = (const float*)d_in[14];
    const float* Wd1    = (const float*)d_in[15];
    const float* bd1    = (const float*)d_in[16];
    const float* Wd2    = (const float*)d_in[17];
    const float* bd2    = (const float*)d_in[18];
    const float* Wd3    = (const float*)d_in[19];
    const float* bd3    = (const float*)d_in[20];
    const float* Wg1    = (const float*)d_in[21];
    const float* bg1    = (const float*)d_in[22];
    const float* Wg2    = (const float*)d_in[23];
    const float* bg2    = (const float*)d_in[24];

    float* out    = (float*)d_out;
    float* out_mu = out;
    float* out_s  = out + (size_t)BATCH * LAT;
    float* out_zp = out + (size_t)2 * BATCH * LAT;   // z_path[t]

    float *bufA, *bufB, *z;
    cudaGetSymbolAddress((void**)&bufA, g_bufA);
    cudaGetSymbolAddress((void**)&bufB, g_bufB);
    cudaGetSymbolAddress((void**)&z,    g_z);

    const dim3 blk(256);
    const dim3 gBig(2, BATCH / 128);    // BM=128, BN=128, N=256
    const dim3 gLat(2, BATCH / 64);     // BM=64,  BN=64,  N=128
    const dim3 gSm(1, BATCH / 64);      // BM=64,  BN=64,  N=64

    const float* NP = nullptr;
    float* NPo = nullptr;

    // ---------------- encoder ----------------
    gemm_k<8, 4, EPI_SWISH><<<gBig, blk>>>(x, HID, HID, W_in, HID, b_in, bufA, HID, NP, NPo);
    for (int i = 0; i < NBLOCKS; ++i) {
        gemm_k<8, 4, EPI_SWISH><<<gBig, blk>>>(bufA, HID, HID,
                                               Wb1 + (size_t)i * HID * HID, HID,
                                               bb1 + (size_t)i * HID, bufB, HID, NP, NPo);
        gemm_k<8, 4, EPI_RES><<<gBig, blk>>>(bufB, HID, HID,
                                             Wb2 + (size_t)i * HID * HID, HID,
                                             bb2 + (size_t)i * HID, bufA, HID, bufA, NPo);
    }
    gemm_k<8, 4, EPI_NONE><<<gBig, blk>>>(bufA, HID, HID, W_fo, HID, b_fo, bufB, HID, NP, NPo);
    gemm_k<4, 2, EPI_LATENT><<<gLat, blk>>>(bufB, HID, HID, W_lat, 2 * LAT, b_lat,
                                            out_mu, LAT, NP, out_s);
    gemm_k<4, 2, EPI_Z0><<<gSm, blk>>>(bufB, HID, HID, W_init, LAT, b_init,
                                       z, LAT, NP, out_zp);

    // ---------------- SDE: ONE persistent 512-thread kernel -----------------
    cudaFuncSetAttribute(sde_kernel,
                         cudaFuncAttributeMaxDynamicSharedMemorySize, SDE_SMEM);
    sde_kernel<<<BATCH / 128, 512, SDE_SMEM>>>(ts, noise,
                                               Wd1, bd1, Wd2, bd2, Wd3, bd3,
                                               Wg1, bg1, Wg2, bg2, out_zp);
}